// round 3
// baseline (speedup 1.0000x reference)
#include <cuda_runtime.h>

// GridToGraphConverter: B=4, C=16, H=W=512
//  out layout (float32, concatenated):
//   [0, NF)            node_features  (B*HW, C)
//   [NF, NF+E)         edge_index src row
//   [NF+E, NF+2E)      edge_index dst row
//   [NF+2E, NF+2E+2E)  edge_attr (E, 2)
// edge_index and edge offsets are generated analytically (grid-8 structure),
// so d_in[1] is never read.

#define Wd 512
#define Hd 512
#define HWd (Wd * Hd)
#define Cc 16
#define Bb 4
#define NFSZ (Bb * HWd * Cc)        // 16777216
#define Ed 2091012

__global__ __launch_bounds__(128) void g2g_kernel(const float* __restrict__ grid,
                                                  float* __restrict__ out) {
    // SMEM transpose buffer: layout [c][node_local], stride 516 (pad for banks,
    // keeps 16B alignment for float4 stores: 516*4 % 16 == 0).
    __shared__ float sm[Cc * 516];

    const int tid = threadIdx.x;
    const int g = blockIdx.x * 128 + tid;   // group id (4 nodes per group)
    const int n0 = g * 4;                   // first node of group (same row)
    const int h = n0 >> 9;
    const int wg = n0 & 511;

    const bool hasUp = (h > 0);
    const bool hasDn = (h < Hd - 1);
    const bool hasL = (wg > 0);
    const bool hasR = (wg < Wd - 4);

    // Clamped (safe) load offsets; garbage values land in acc slots that are
    // never emitted.
    const int oUpC = hasUp ? n0 - 512 : n0;
    const int oUpL = (hasUp && hasL) ? n0 - 513 : n0;
    const int oUpR = (hasUp && hasR) ? n0 - 508 : n0;
    const int oL   = hasL ? n0 - 1 : n0;
    const int oR   = hasR ? n0 + 4 : n0;
    const int oDnC = hasDn ? n0 + 512 : n0;
    const int oDnL = (hasDn && hasL) ? n0 + 511 : n0;
    const int oDnR = (hasDn && hasR) ? n0 + 516 : n0;

    float acc[4][8];
#pragma unroll
    for (int i = 0; i < 4; i++)
#pragma unroll
        for (int k = 0; k < 8; k++) acc[i][k] = 0.0f;

    const int blockN0 = blockIdx.x * 512;   // first node of this block

    for (int b = 0; b < Bb; b++) {
        const float* pb = grid + (size_t)b * (Cc * HWd);
#pragma unroll 4
        for (int c = 0; c < Cc; c++) {
            const float* p = pb + (size_t)c * HWd;
            float4 ow = *(const float4*)(p + n0);
            // stash own values for the coalesced transpose write
            *(float4*)(&sm[c * 516 + tid * 4]) = ow;

            float4 up = *(const float4*)(p + oUpC);
            float4 dn = *(const float4*)(p + oDnC);
            float uL = p[oUpL], uR = p[oUpR];
            float mL = p[oL],   mR = p[oR];
            float dL = p[oDnL], dR = p[oDnR];

            float u[6] = {uL, up.x, up.y, up.z, up.w, uR};
            float m[6] = {mL, ow.x, ow.y, ow.z, ow.w, mR};
            float d[6] = {dL, dn.x, dn.y, dn.z, dn.w, dR};
#pragma unroll
            for (int i = 0; i < 4; i++) {
                float o = m[i + 1];
                acc[i][0] += fabsf(o - u[i]);
                acc[i][1] += fabsf(o - u[i + 1]);
                acc[i][2] += fabsf(o - u[i + 2]);
                acc[i][3] += fabsf(o - m[i]);
                acc[i][4] += fabsf(o - m[i + 2]);
                acc[i][5] += fabsf(o - d[i]);
                acc[i][6] += fabsf(o - d[i + 1]);
                acc[i][7] += fabsf(o - d[i + 2]);
            }
        }
        __syncthreads();
        // Coalesced write of node_features for this batch:
        // 512 nodes * 16 channels contiguous at (b*HW + blockN0)*16.
        float* dst = out + (size_t)b * HWd * Cc + (size_t)blockN0 * Cc;
#pragma unroll
        for (int j = 0; j < 16; j++) {
            int f = (tid + j * 128) * 4;    // flat float index within block tile
            int n = f >> 4;                 // local node
            int c = f & 15;                 // channel (multiple of 4)
            float4 v;
            v.x = sm[(c + 0) * 516 + n];
            v.y = sm[(c + 1) * 516 + n];
            v.z = sm[(c + 2) * 516 + n];
            v.w = sm[(c + 3) * 516 + n];
            *(float4*)(dst + f) = v;
        }
        __syncthreads();
    }

    // ---- Emit edges (index + attr) for the 4 owned nodes ----
    const float SQ2 = 1.41421356237309515f;
    const float dist[8] = {SQ2, 1.0f, SQ2, 1.0f, 1.0f, SQ2, 1.0f, SQ2};
    const int dnk[8] = {-513, -512, -511, -1, 1, 511, 512, 513};
    const float inv64 = 1.0f / 64.0f;

    float* eiS = out + NFSZ;
    float* eiD = out + NFSZ + Ed;
    float* ea  = out + NFSZ + 2 * Ed;

    // Edge-offset closed form:
    //  boundary rows contribute 5W-4 edges, interior rows 8W-6.
    const int rowBase = (h == 0) ? 0 : (5 * Wd - 4) + (h - 1) * (8 * Wd - 6);
    const bool boundaryRow = (h == 0) || (h == Hd - 1);

#pragma unroll
    for (int i = 0; i < 4; i++) {
        int n = n0 + i;
        int w = wg + i;
        int within;
        if (boundaryRow)
            within = (w == 0) ? 0 : 3 + (w - 1) * 5;
        else
            within = (w == 0) ? 0 : 5 + (w - 1) * 8;
        int e = rowBase + within;

        bool vL = (i > 0) || hasL;
        bool vR = (i < 3) || hasR;
        bool val[8] = {hasUp && vL, hasUp, hasUp && vR,
                       vL, vR,
                       hasDn && vL, hasDn, hasDn && vR};
#pragma unroll
        for (int k = 0; k < 8; k++) {
            if (val[k]) {
                eiS[e] = (float)n;
                eiD[e] = (float)(n + dnk[k]);
                ea[2 * e]     = dist[k];
                ea[2 * e + 1] = acc[i][k] * inv64;
                e++;
            }
        }
    }
}

extern "C" void kernel_launch(void* const* d_in, const int* in_sizes, int n_in,
                              void* d_out, int out_size) {
    const float* grid = (const float*)d_in[0];
    float* out = (float*)d_out;
    // 262144 nodes / 4 per thread / 128 threads per block = 512 blocks
    g2g_kernel<<<512, 128>>>(grid, out);
}